// round 6
// baseline (speedup 1.0000x reference)
#include <cuda_runtime.h>
#include <math.h>

#define BETA 0.1f

__device__ __forceinline__ unsigned smem_u32(const void* p) {
    unsigned a;
    asm("{ .reg .u64 t; cvta.to.shared.u64 t, %1; cvt.u32.u64 %0, t; }"
        : "=r"(a) : "l"(p));
    return a;
}

// One block per (b,p) tile, 256 threads.
// Products are staged in SMEM (16 KB per output tensor), then written to
// global via two cp.async.bulk stores (TMA path, bypasses L1tex and the
// per-thread STG pipeline).
__global__ __launch_bounds__(256, 6)
void spatial_sampler_kernel(const float* __restrict__ x_cat,
                            const float* __restrict__ noise,
                            float* __restrict__ out,
                            long long half_elems)
{
    __shared__ float sx[128];    // [0:64) h row, [64:128) v row
    __shared__ float ss[128];    // masked rows (h part pre-scaled by 100)
    __shared__ float wmax[4];
    __shared__ __align__(16) float tile[2][4096];   // [0]=places, [1]=sampled

    const int bp  = blockIdx.x;
    const int tid = threadIdx.x;

    const float* xrow = x_cat + (long long)bp * 128;
    const float* nrow = noise + (long long)bp * 128;

    // --- load + log_pdf + per-row max (each 64-wide row = 2 warps) ---
    float lp = -INFINITY;
    float xv = 0.f;
    if (tid < 128) {
        xv = xrow[tid];
        lp = logf(xv) + BETA * nrow[tid];
        sx[tid] = xv;
    }
    float m = lp;
    #pragma unroll
    for (int off = 16; off > 0; off >>= 1)
        m = fmaxf(m, __shfl_xor_sync(0xffffffffu, m, off));
    if (tid < 128 && (tid & 31) == 0)
        wmax[tid >> 5] = m;
    __syncthreads();

    if (tid < 128) {
        float rowmax = (tid < 64) ? fmaxf(wmax[0], wmax[1])
                                  : fmaxf(wmax[2], wmax[3]);
        float s = (lp == rowmax) ? xv : 0.f;
        ss[tid] = (tid < 64) ? s * 100.0f : s;   // fold *100 into h half
    }
    __syncthreads();

    // --- compute products into SMEM tiles (half-block per tensor) ---
    {
        const int  half_tid = tid & 127;
        const int  sel      = tid >> 7;          // 0 -> places, 1 -> sampled
        const float* hsrc = sel ? ss : sx;
        const float4* v4  = reinterpret_cast<const float4*>(sel ? &ss[64] : &sx[64]);
        float4* t4 = reinterpret_cast<float4*>(tile[sel]);

        #pragma unroll
        for (int it = 0; it < 8; ++it) {
            const int i  = half_tid + it * 128;   // float4 index 0..1023
            const int j  = i >> 4;                // row
            const int c4 = i & 15;                // float4 col
            const float hj = hsrc[j];
            float4 vv = v4[c4];
            float4 o;
            o.x = hj * vv.x; o.y = hj * vv.y; o.z = hj * vv.z; o.w = hj * vv.w;
            t4[i] = o;
        }
    }
    __syncthreads();

    // --- bulk TMA stores: SMEM -> GMEM, 16 KB each, bypassing L1 ---
    if (tid == 0) {
        asm volatile("fence.proxy.async.shared::cta;" ::: "memory");
        float* gp = out + (long long)bp * 4096;
        float* gs = out + half_elems + (long long)bp * 4096;
        unsigned sp = smem_u32(tile[0]);
        unsigned sq = smem_u32(tile[1]);
        asm volatile("cp.async.bulk.global.shared::cta.bulk_group [%0], [%1], %2;"
                     :: "l"(gp), "r"(sp), "n"(16384) : "memory");
        asm volatile("cp.async.bulk.global.shared::cta.bulk_group [%0], [%1], %2;"
                     :: "l"(gs), "r"(sq), "n"(16384) : "memory");
        asm volatile("cp.async.bulk.commit_group;" ::: "memory");
        asm volatile("cp.async.bulk.wait_group.read 0;" ::: "memory");
    }
}

extern "C" void kernel_launch(void* const* d_in, const int* in_sizes, int n_in,
                              void* d_out, int out_size)
{
    const float* x_cat = (const float*)d_in[0];
    const float* noise = (const float*)d_in[1];
    float* out = (float*)d_out;

    const long long half = (long long)out_size / 2;
    const int tiles = in_sizes[0] / 128;   // 8192 (b,p) tiles

    spatial_sampler_kernel<<<tiles, 256>>>(x_cat, noise, out, half);
}

// round 7
// speedup vs baseline: 1.0056x; 1.0056x over previous
#include <cuda_runtime.h>
#include <math.h>

#define BETA 0.1f
// Tiles [0, RESIDENT_TILES) are stored with L2 evict_last so they stay
// resident across graph replays (2*16KB*3200 = 100 MB < 126 MB L2).
// The rest stream with evict_first so they can't thrash the resident set.
#define RESIDENT_TILES 3200

__global__ __launch_bounds__(256, 8)
void spatial_sampler_kernel(const float* __restrict__ x_cat,
                            const float* __restrict__ noise,
                            float* __restrict__ out,
                            long long half_elems)
{
    __shared__ float sx[128];   // [0:64) h row, [64:128) v row
    __shared__ float ss[128];   // masked rows (h part pre-scaled by 100)
    __shared__ float wmax[4];

    const int bp  = blockIdx.x;
    const int tid = threadIdx.x;

    const float* xrow = x_cat + (long long)bp * 128;
    const float* nrow = noise + (long long)bp * 128;

    // --- load + log_pdf + per-row max (each 64-wide row = 2 warps) ---
    float lp = -INFINITY;
    float xv = 0.f;
    if (tid < 128) {
        xv = xrow[tid];
        lp = logf(xv) + BETA * nrow[tid];
        sx[tid] = xv;
    }
    float m = lp;
    #pragma unroll
    for (int off = 16; off > 0; off >>= 1)
        m = fmaxf(m, __shfl_xor_sync(0xffffffffu, m, off));
    if (tid < 128 && (tid & 31) == 0)
        wmax[tid >> 5] = m;
    __syncthreads();

    if (tid < 128) {
        float rowmax = (tid < 64) ? fmaxf(wmax[0], wmax[1])
                                  : fmaxf(wmax[2], wmax[3]);
        float s = (lp == rowmax) ? xv : 0.f;
        ss[tid] = (tid < 64) ? s * 100.0f : s;   // fold *100 into h half
    }
    __syncthreads();

    // --- L2 residency policy for this tile ---
    unsigned long long pol;
    if (bp < RESIDENT_TILES)
        asm("createpolicy.fractional.L2::evict_last.b64 %0, 1.0;"  : "=l"(pol));
    else
        asm("createpolicy.fractional.L2::evict_first.b64 %0, 1.0;" : "=l"(pol));

    // --- de-interleaved stores: half-block per output tensor ---
    const int  half_tid = tid & 127;          // 0..127 within half-block
    const bool is_samp  = (tid >= 128);

    const float* hsrc = is_samp ? ss      : sx;
    const float4* v4  = reinterpret_cast<const float4*>(is_samp ? &ss[64] : &sx[64]);
    float4* dst = reinterpret_cast<float4*>(
        out + (is_samp ? half_elems : 0) + (long long)bp * 4096);

    #pragma unroll
    for (int it = 0; it < 8; ++it) {
        const int i  = half_tid + it * 128;   // float4 index 0..1023
        const int j  = i >> 4;                // row 0..63
        const int c4 = i & 15;                // float4 col 0..15

        const float hj = hsrc[j];
        float4 vv = v4[c4];
        float4 o;
        o.x = hj * vv.x; o.y = hj * vv.y; o.z = hj * vv.z; o.w = hj * vv.w;
        asm volatile("st.global.L2::cache_hint.v4.f32 [%0], {%1,%2,%3,%4}, %5;"
                     :: "l"(dst + i), "f"(o.x), "f"(o.y), "f"(o.z), "f"(o.w),
                        "l"(pol)
                     : "memory");
    }
}

extern "C" void kernel_launch(void* const* d_in, const int* in_sizes, int n_in,
                              void* d_out, int out_size)
{
    const float* x_cat = (const float*)d_in[0];
    const float* noise = (const float*)d_in[1];
    float* out = (float*)d_out;

    const long long half = (long long)out_size / 2;
    const int tiles = in_sizes[0] / 128;   // 8192 (b,p) tiles

    spatial_sampler_kernel<<<tiles, 256>>>(x_cat, noise, out, half);
}